// round 1
// baseline (speedup 1.0000x reference)
#include <cuda_runtime.h>

// CANN recurrent net: 14 iterations of
//   y  = J @ s_prev                (deferred-normalized matvec)
//   U  = y / recSum_prev + Iext
//   s  = (0.2*U)^2
//   recSum = K * sum(s)
// Outputs: U_14 (1680), recSum_14 (1), r_14 = s_14/recSum_14 (1680)

#define Nn     1680
#define NB     148
#define TPB    384          // 12 warps
#define NWARP  12
#define ITERS  14
#define KC     0.005f
#define NF4    420          // 1680/4
#define FULL4  416          // 13*32 float4 per lane-group

__device__ float            g_s[2][Nn];        // unnormalized sq vectors, double-buffered
__device__ float            g_partial[2][NB];  // per-block partial sums, double-buffered
__device__ volatile unsigned g_epoch;          // monotonic barrier epoch (reset-free)
__device__ unsigned          g_count;          // barrier arrival counter (self-resetting)

__global__ void __launch_bounds__(TPB, 1)
cann_kernel(const float* __restrict__ net_in,
            const float* __restrict__ J,
            float* __restrict__ out)
{
    __shared__ float s_sm[Nn];      // staged s vector (6720 B)
    __shared__ float s_warp[NWARP]; // block partial reduce scratch
    __shared__ float s_rs;          // broadcast (1/recSum_prev) or recSum

    const int tid  = threadIdx.x;
    const int lane = tid & 31;
    const int wid  = tid >> 5;
    const int bid  = blockIdx.x;
    // Balanced row assignment: every block owns 11-12 active rows.
    const int row  = wid * NB + bid;
    const bool active = (row < Nn);

    // Epoch base: safe to read here — the first barrier cannot complete
    // until every block has arrived, and each block reads e0 before arriving.
    unsigned e0 = 0;
    if (tid == 0) e0 = g_epoch;

    const float* Iext = net_in;
    const float* r0   = net_in + Nn;

    float lastS = 0.f;   // s value at final iteration (kept in lane 0 of owning warp)

    for (int t = 1; t <= ITERS; ++t) {
        const int parPrev = (t - 1) & 1;
        const int parCur  = t & 1;

        // --- recSum_{t-1} from double-buffered partials (warp 0) ---
        if (t > 1 && wid == 0) {
            float rs = 0.f;
            for (int i = lane; i < NB; i += 32)
                rs += __ldcg(&g_partial[parPrev][i]);
            #pragma unroll
            for (int o = 16; o; o >>= 1) rs += __shfl_xor_sync(0xffffffffu, rs, o);
            if (lane == 0) s_rs = 1.0f / (KC * rs);
        }

        // --- stage s_{t-1} into smem ---
        if (t == 1) {
            for (int i = tid; i < Nn; i += TPB) s_sm[i] = r0[i];
        } else {
            const float* sp = g_s[parPrev];
            for (int i = tid; i < Nn; i += TPB) s_sm[i] = __ldcg(&sp[i]);
        }
        __syncthreads();
        const float invDen = (t == 1) ? 1.0f : s_rs;

        // --- matvec: one warp per row ---
        float sval = 0.f;
        if (active) {
            const float4* Jr = reinterpret_cast<const float4*>(J + (size_t)row * Nn);
            const float4* s4 = reinterpret_cast<const float4*>(s_sm);
            float acc = 0.f;
            #pragma unroll
            for (int j = 0; j < 13; ++j) {
                float4 a = __ldg(&Jr[j * 32 + lane]);
                float4 b = s4[j * 32 + lane];
                acc = fmaf(a.x, b.x, acc);
                acc = fmaf(a.y, b.y, acc);
                acc = fmaf(a.z, b.z, acc);
                acc = fmaf(a.w, b.w, acc);
            }
            if (lane < (NF4 - FULL4)) {     // tail: 4 float4 (16 floats)
                float4 a = __ldg(&Jr[FULL4 + lane]);
                float4 b = s4[FULL4 + lane];
                acc = fmaf(a.x, b.x, acc);
                acc = fmaf(a.y, b.y, acc);
                acc = fmaf(a.z, b.z, acc);
                acc = fmaf(a.w, b.w, acc);
            }
            #pragma unroll
            for (int o = 16; o; o >>= 1) acc += __shfl_xor_sync(0xffffffffu, acc, o);
            if (lane == 0) {
                float U  = fmaf(acc, invDen, Iext[row]);
                float u2 = 0.2f * U;
                sval = u2 * u2;
                __stcg(&g_s[parCur][row], sval);
                if (t == ITERS) { out[row] = U; lastS = sval; }
            }
        }

        // --- per-block partial sum of s_t ---
        if (lane == 0) s_warp[wid] = sval;
        __syncthreads();
        if (tid == 0) {
            float p = 0.f;
            #pragma unroll
            for (int w = 0; w < NWARP; ++w) p += s_warp[w];
            __stcg(&g_partial[parCur][bid], p);
        }

        // --- grid barrier (monotonic epoch, self-resetting count) ---
        __syncthreads();
        if (tid == 0) {
            __threadfence();
            unsigned old = atomicAdd(&g_count, 1u);
            if (old == (unsigned)(NB - 1)) {
                atomicExch(&g_count, 0u);
                __threadfence();
                atomicAdd((unsigned*)&g_epoch, 1u);
            } else {
                while ((unsigned)(g_epoch - e0) < (unsigned)t) { /* spin */ }
                __threadfence();
            }
        }
        __syncthreads();
    }

    // --- final outputs: recSum_14 and r_14 = s_14 / recSum_14 ---
    if (wid == 0) {
        float rs = 0.f;
        for (int i = lane; i < NB; i += 32)
            rs += __ldcg(&g_partial[ITERS & 1][i]);
        #pragma unroll
        for (int o = 16; o; o >>= 1) rs += __shfl_xor_sync(0xffffffffu, rs, o);
        if (lane == 0) s_rs = KC * rs;
    }
    __syncthreads();
    const float recS = s_rs;
    if (bid == 0 && tid == 0) out[Nn] = recS;
    if (active && lane == 0) out[Nn + 1 + row] = lastS / recS;
}

extern "C" void kernel_launch(void* const* d_in, const int* in_sizes, int n_in,
                              void* d_out, int out_size)
{
    const float* a = (const float*)d_in[0];
    const float* b = (const float*)d_in[1];
    const float* net_in = a;
    const float* J      = b;
    if (n_in >= 2 && in_sizes[0] > in_sizes[1]) { net_in = b; J = a; }
    cann_kernel<<<NB, TPB>>>(net_in, J, (float*)d_out);
}

// round 2
// speedup vs baseline: 1.7603x; 1.7603x over previous
#include <cuda_runtime.h>

// CANN recurrent net, 14 iterations:
//   y_t  = J @ s_{t-1}            (deferred normalization)
//   U_t  = y_t / recSum_{t-1} + Iext     (recSum_0 absent: s_0 = r0)
//   s_t  = (0.2*U_t)^2
//   recSum_t = K * sum(s_t)
// Outputs: U_14 (1680), recSum_14 (1), r_14 = s_14/recSum_14 (1680)
//
// Design: persistent grid (148 blocks = 1/SM), J row register-resident per warp,
// grid sync via tagged-broadcast slots (tag monotonic across graph replays).

#define Nn     1680
#define NB     148
#define TPB    384          // 12 warps
#define NWARP  12
#define ITERS  14
#define KC     0.005f

__device__ float              g_s[2][Nn];      // unnormalized s vectors, parity-buffered
__device__ unsigned long long g_slot[2][NB];   // {tag:32 | partial-bits:32}, parity-buffered

__device__ __forceinline__ unsigned long long ld_slot(const unsigned long long* p) {
    unsigned long long v;
    asm volatile("ld.global.cg.u64 %0, [%1];" : "=l"(v) : "l"(p));
    return v;
}
__device__ __forceinline__ void st_slot(unsigned long long* p, unsigned long long v) {
    asm volatile("st.global.cg.u64 [%0], %1;" :: "l"(p), "l"(v) : "memory");
}

// Warp-0 poll: wait until all NB slots of given parity carry `target` tag,
// return K-independent deterministic sum of their partials (fixed slot order).
__device__ __forceinline__ float poll_sum(int par, unsigned target, int lane) {
    float vals[5];
    unsigned got = 0, need = 0;
    #pragma unroll
    for (int k = 0; k < 5; ++k) {
        vals[k] = 0.f;
        if (lane + 32 * k < NB) need |= 1u << k;
    }
    while (got != need) {
        #pragma unroll
        for (int k = 0; k < 5; ++k) {
            int s = lane + 32 * k;
            if (((need >> k) & 1u) && !((got >> k) & 1u)) {
                unsigned long long x = ld_slot(&g_slot[par][s]);
                if ((unsigned)(x >> 32) == target) {
                    vals[k] = __uint_as_float((unsigned)(x & 0xffffffffull));
                    got |= 1u << k;
                }
            }
        }
    }
    float rs = ((vals[0] + vals[1]) + (vals[2] + vals[3])) + vals[4];
    #pragma unroll
    for (int o = 16; o; o >>= 1) rs += __shfl_xor_sync(0xffffffffu, rs, o);
    return rs;   // uniform across the warp
}

__global__ void __launch_bounds__(TPB, 1)
cann_kernel(const float* __restrict__ net_in,
            const float* __restrict__ J,
            float* __restrict__ out)
{
    __shared__ float s_sm[Nn];       // staged s vector (6720 B)
    __shared__ float s_warp[NWARP];
    __shared__ float s_inv;          // broadcast 1/recSum (or recSum in epilogue)

    const int tid  = threadIdx.x;
    const int lane = tid & 31;
    const int wid  = tid >> 5;
    const int bid  = blockIdx.x;
    const int row  = wid * NB + bid;          // balanced: 11-12 rows/block
    const bool active = (row < Nn);

    // Monotonic tag base: own slot's last tag (previous run ended at parity ITERS&1==0).
    // Safe: only this block ever writes its slot; all blocks ended at the same tag.
    const unsigned base = (unsigned)(ld_slot(&g_slot[0][bid]) >> 32);

    const float iext = active ? __ldg(&net_in[row]) : 0.f;

    // ---- prologue: J row -> registers (row length 1680 = 13*128 + 16 floats) ----
    float4 Jr[14];
    if (active) {
        const float4* Jp = reinterpret_cast<const float4*>(J + (size_t)row * Nn);
        #pragma unroll
        for (int j = 0; j < 13; ++j) Jr[j] = __ldg(&Jp[j * 32 + lane]);
        Jr[13] = (lane < 4) ? __ldg(&Jp[416 + lane]) : make_float4(0.f, 0.f, 0.f, 0.f);
    }

    float lastS = 0.f;

    for (int t = 1; t <= ITERS; ++t) {
        // ---- acquire s_{t-1} (and recSum_{t-1} for t>1) ----
        if (t == 1) {
            const float4* r4 = reinterpret_cast<const float4*>(net_in + Nn);
            for (int i = tid; i < Nn / 4; i += TPB)
                reinterpret_cast<float4*>(s_sm)[i] = __ldg(&r4[i]);
        } else {
            const int par = (t - 1) & 1;
            if (wid == 0) {
                float rs = poll_sum(par, base + (unsigned)(t - 1), lane);
                if (lane == 0) s_inv = 1.0f / (KC * rs);
                __threadfence();   // acquire: order g_s reads after tag observation
            }
            __syncthreads();       // release all warps past the grid sync
            const float4* sp4 = reinterpret_cast<const float4*>(g_s[par]);
            for (int i = tid; i < Nn / 4; i += TPB)
                reinterpret_cast<float4*>(s_sm)[i] = __ldcg(&sp4[i]);
        }
        __syncthreads();
        const float invDen = (t == 1) ? 1.0f : s_inv;

        // ---- matvec: register-resident J row  x  smem s ----
        float sval = 0.f;
        if (active) {
            const float4* s4 = reinterpret_cast<const float4*>(s_sm);
            float acc = 0.f;
            #pragma unroll
            for (int j = 0; j < 13; ++j) {
                float4 b = s4[j * 32 + lane];
                acc = fmaf(Jr[j].x, b.x, acc);
                acc = fmaf(Jr[j].y, b.y, acc);
                acc = fmaf(Jr[j].z, b.z, acc);
                acc = fmaf(Jr[j].w, b.w, acc);
            }
            if (lane < 4) {
                float4 b = s4[416 + lane];
                acc = fmaf(Jr[13].x, b.x, acc);
                acc = fmaf(Jr[13].y, b.y, acc);
                acc = fmaf(Jr[13].z, b.z, acc);
                acc = fmaf(Jr[13].w, b.w, acc);
            }
            #pragma unroll
            for (int o = 16; o; o >>= 1) acc += __shfl_xor_sync(0xffffffffu, acc, o);
            if (lane == 0) {
                float U  = fmaf(acc, invDen, iext);
                float u2 = 0.2f * U;
                sval = u2 * u2;
                __stcg(&g_s[t & 1][row], sval);
                if (t == ITERS) { out[row] = U; lastS = sval; }
            }
        }

        // ---- block partial + tagged slot publish (release) ----
        if (lane == 0) s_warp[wid] = sval;
        __syncthreads();
        if (tid == 0) {
            float p = 0.f;
            #pragma unroll
            for (int w = 0; w < NWARP; ++w) p += s_warp[w];
            __threadfence();   // release: s values reach L2 before the tag
            unsigned long long pk =
                ((unsigned long long)(base + (unsigned)t) << 32) |
                (unsigned long long)__float_as_uint(p);
            st_slot(&g_slot[t & 1][bid], pk);
        }
        // no extra barrier: laggard warps are held at the next iteration's
        // post-poll __syncthreads, which warp 0 only passes after polling.
    }

    // ---- epilogue: global recSum_14, then r_14 = s_14 / recSum_14 ----
    if (wid == 0) {
        float rs = poll_sum(ITERS & 1, base + (unsigned)ITERS, lane);
        if (lane == 0) s_inv = KC * rs;
    }
    __syncthreads();
    const float recS = s_inv;
    if (bid == 0 && tid == 0) out[Nn] = recS;
    if (active && lane == 0)  out[Nn + 1 + row] = lastS / recS;
}

extern "C" void kernel_launch(void* const* d_in, const int* in_sizes, int n_in,
                              void* d_out, int out_size)
{
    const float* a = (const float*)d_in[0];
    const float* b = (const float*)d_in[1];
    const float* net_in = a;
    const float* J      = b;
    if (n_in >= 2 && in_sizes[0] > in_sizes[1]) { net_in = b; J = a; }
    cann_kernel<<<NB, TPB>>>(net_in, J, (float*)d_out);
}